// round 9
// baseline (speedup 1.0000x reference)
#include <cuda_runtime.h>
#include <math.h>

namespace {

constexpr int T   = 512;
constexpr int D   = 512;
constexpr int Bb  = 16;
constexpr int DT  = 16;          // d-tile per CTA
constexpr int NTH = 256;
constexpr int NTILES = D / DT;   // 32
constexpr int NCTA = NTILES * Bb; // 512
constexpr int F   = 255;         // freq bins 1..255
constexpr float TWO_PI = 6.2831853071795864769f;
constexpr float SSCALE = 2.0f / (float)T;     // season scale
constexpr float SSCALE2 = 4.0f / (float)T;    // 2 * season scale

struct alignas(16) ULL2 { unsigned long long x, y; };

struct Smem {
    float  bufB[8224];    // phase1: e[t*16+dd] (t=1..255) @0, o @+4096; phase3+: cs prefix (513*16)
    float  scratch[8192]; // x (load) -> Re/Im (255*16 float2) -> x_rem (512*16)
    float2 tab[T];        // (cos, sin)(2*pi*j/512)
    float  wl[T];         // W_lin
    float  wt[8], bt[8];  // W_trend, b_trend (6 used)
    int    selk[DT][4];   // selected freq index k (1..255)
    float  selRe[DT][4];
    float  selIm[DT][4];
    float  x0row[DT], x256row[DT];
    float  xr0[DT], xrL[DT];
    float  red[NTH];
    int    done_flag;
};

__device__ float g_xtrans[Bb * D];
__device__ unsigned int g_arrive = 0;

} // namespace

#define FMA2(d, a, b, c) asm("fma.rn.f32x2 %0, %1, %2, %3;" : "=l"(d) : "l"(a), "l"(b), "l"(c))
#define PACK2(d, x)      asm("mov.b64 %0, {%1, %1};" : "=l"(d) : "f"(x))
#define PACK2P(d, lo, hi) asm("mov.b64 %0, {%1, %2};" : "=l"(d) : "f"(lo), "f"(hi))
#define UNPACK2(lo, hi, s) asm("mov.b64 {%0, %1}, %2;" : "=f"(lo), "=f"(hi) : "l"(s))

__global__ __launch_bounds__(NTH, 3) void msr_main(
    const float* __restrict__ x,
    const float* __restrict__ wt_g,
    const float* __restrict__ bt_g,
    const float* __restrict__ wl_g,
    const float* __restrict__ bl_g,
    const float* __restrict__ noise,
    const float* __restrict__ Wr, const float* __restrict__ br,
    const float* __restrict__ Wn, const float* __restrict__ bn,
    float* __restrict__ out)
{
    extern __shared__ unsigned char smem_raw[];
    Smem& sm = *reinterpret_cast<Smem*>(smem_raw);

    const int tid = threadIdx.x;
    const int b   = blockIdx.y;
    const int d0  = blockIdx.x * DT;

    // ---- init tables ----
    for (int j = tid; j < T; j += NTH) {
        float s, c;
        sincosf(TWO_PI * (float)j / (float)T, &s, &c);
        sm.tab[j] = make_float2(c, s);
        sm.wl[j]  = wl_g[j];
    }
    if (tid < 6) { sm.wt[tid] = wt_g[tid]; sm.bt[tid] = bt_g[tid]; }

    // ---- load x tile into scratch: scratch[t*16 + dd] = x[b, t, d0+dd] ----
    {
        const float* xb = x + (size_t)b * T * D + d0;
        const int q = (tid & 3) * 4;
        const int t0 = tid >> 2;
        #pragma unroll
        for (int i = 0; i < 8; i++) {
            int t = t0 + 64 * i;
            float4 v = *reinterpret_cast<const float4*>(xb + (size_t)t * D + q);
            *reinterpret_cast<float4*>(&sm.scratch[t * DT + q]) = v;
        }
    }
    __syncthreads();

    // ---- Phase 1a: even/odd precompute e[t]=x[t]+x[512-t], o[t]=x[t]-x[512-t] ----
    {
        for (int idx = tid; idx < 255 * DT; idx += NTH) {
            int t = (idx >> 4) + 1, dd = idx & 15;
            float a  = sm.scratch[t * DT + dd];
            float bb = sm.scratch[(T - t) * DT + dd];
            sm.bufB[t * DT + dd]        = a + bb;
            sm.bufB[4096 + t * DT + dd] = a - bb;
        }
        if (tid < DT) {
            sm.x0row[tid]   = sm.scratch[tid];
            sm.x256row[tid] = sm.scratch[256 * DT + tid];
        }
    }
    __syncthreads();

    // ---- Phase 1: half-range DFT, thread owns freqs (fi, fi+128), 8 d's ----
    {
        const int fi   = (tid & 127) + 1;    // 1..128
        const int doff = (tid >> 7) * 8;     // 0 or 8
        const float* ce = sm.bufB;
        const float* co = sm.bufB + 4096;

        unsigned long long aAR[4], aAI[4], aBR[4], aBI[4];
        const float sgn = (fi & 1) ? -1.f : 1.f;   // (-1)^fi = (-1)^(fi+128)
        #pragma unroll
        for (int q = 0; q < 4; q++) {
            float2 v0 = *reinterpret_cast<const float2*>(&sm.x0row[doff + q * 2]);
            float2 v2 = *reinterpret_cast<const float2*>(&sm.x256row[doff + q * 2]);
            float lo = fmaf(sgn, v2.x, v0.x);
            float hi = fmaf(sgn, v2.y, v0.y);
            PACK2P(aAR[q], lo, hi);
            aBR[q] = aAR[q];
            aAI[q] = 0ull; aBI[q] = 0ull;
        }

        // peel t = 1..3 (exact table twiddles for both freqs)
        #pragma unroll
        for (int t = 1; t <= 3; t++) {
            float2 ea = sm.tab[(fi * t) & (T - 1)];
            float2 eb = sm.tab[((fi + 128) * t) & (T - 1)];
            unsigned long long cA2, nsA2, cB2, nsB2;
            float na = -ea.y, nb = -eb.y;
            PACK2(cA2, ea.x); PACK2(nsA2, na);
            PACK2(cB2, eb.x); PACK2(nsB2, nb);
            const ULL2* ep = reinterpret_cast<const ULL2*>(&ce[t * DT + doff]);
            const ULL2* op = reinterpret_cast<const ULL2*>(&co[t * DT + doff]);
            ULL2 e0 = ep[0], e1 = ep[1];
            ULL2 o0 = op[0], o1 = op[1];
            FMA2(aAR[0], e0.x, cA2, aAR[0]); FMA2(aAR[1], e0.y, cA2, aAR[1]);
            FMA2(aAR[2], e1.x, cA2, aAR[2]); FMA2(aAR[3], e1.y, cA2, aAR[3]);
            FMA2(aAI[0], o0.x, nsA2, aAI[0]); FMA2(aAI[1], o0.y, nsA2, aAI[1]);
            FMA2(aAI[2], o1.x, nsA2, aAI[2]); FMA2(aAI[3], o1.y, nsA2, aAI[3]);
            FMA2(aBR[0], e0.x, cB2, aBR[0]); FMA2(aBR[1], e0.y, cB2, aBR[1]);
            FMA2(aBR[2], e1.x, cB2, aBR[2]); FMA2(aBR[3], e1.y, cB2, aBR[3]);
            FMA2(aBI[0], o0.x, nsB2, aBI[0]); FMA2(aBI[1], o0.y, nsB2, aBI[1]);
            FMA2(aBI[2], o1.x, nsB2, aBI[2]); FMA2(aBI[3], o1.y, nsB2, aBI[3]);
        }

        // main loop t = 4..255 in unroll-4 groups; freq B twiddle = A twiddle * i^t
        const float2 w = sm.tab[fi];
        const float cw = w.x, sw = w.y;
        float cr = 1.f, si = 0.f;
        #pragma unroll 1
        for (int g = 0; g < 63; g++) {
            const int t0 = 4 + g * 4;
            if ((t0 & 63) == 4) {                // resync from exact table
                float2 e = sm.tab[(fi * t0) & (T - 1)];
                cr = e.x; si = e.y;
            }
            #pragma unroll
            for (int j = 0; j < 4; j++) {
                const int t = t0 + j;
                unsigned long long c2, s2, nc2, ns2;
                float nc = -cr, ns = -si;
                PACK2(c2, cr); PACK2(s2, si);
                PACK2(nc2, nc); PACK2(ns2, ns);
                const ULL2* ep = reinterpret_cast<const ULL2*>(&ce[t * DT + doff]);
                const ULL2* op = reinterpret_cast<const ULL2*>(&co[t * DT + doff]);
                ULL2 e0 = ep[0], e1 = ep[1];
                ULL2 o0 = op[0], o1 = op[1];
                // freq A: cos=c, -sin=-s
                FMA2(aAR[0], e0.x, c2, aAR[0]); FMA2(aAR[1], e0.y, c2, aAR[1]);
                FMA2(aAR[2], e1.x, c2, aAR[2]); FMA2(aAR[3], e1.y, c2, aAR[3]);
                FMA2(aAI[0], o0.x, ns2, aAI[0]); FMA2(aAI[1], o0.y, ns2, aAI[1]);
                FMA2(aAI[2], o1.x, ns2, aAI[2]); FMA2(aAI[3], o1.y, ns2, aAI[3]);
                // freq B = A rotated by i^t (t mod 4 == j):
                //  j=0: cB=c,  -sB=-s ; j=1: cB=-s, -sB=-c
                //  j=2: cB=-c, -sB=+s ; j=3: cB=+s, -sB=+c
                unsigned long long cB2  = (j == 0) ? c2  : (j == 1) ? ns2 : (j == 2) ? nc2 : s2;
                unsigned long long nsB2 = (j == 0) ? ns2 : (j == 1) ? nc2 : (j == 2) ? s2  : c2;
                FMA2(aBR[0], e0.x, cB2, aBR[0]); FMA2(aBR[1], e0.y, cB2, aBR[1]);
                FMA2(aBR[2], e1.x, cB2, aBR[2]); FMA2(aBR[3], e1.y, cB2, aBR[3]);
                FMA2(aBI[0], o0.x, nsB2, aBI[0]); FMA2(aBI[1], o0.y, nsB2, aBI[1]);
                FMA2(aBI[2], o1.x, nsB2, aBI[2]); FMA2(aBI[3], o1.y, nsB2, aBI[3]);
                // advance twiddle by one step
                float cn = cr * cw - si * sw;
                si = fmaf(si, cw, cr * sw);
                cr = cn;
            }
        }

        // write Re/Im into scratch (x is dead; x0/x256 saved)
        float2* ri = reinterpret_cast<float2*>(sm.scratch);
        #pragma unroll
        for (int q = 0; q < 4; q++) {
            float rlo, rhi, ilo, ihi;
            UNPACK2(rlo, rhi, aAR[q]);
            UNPACK2(ilo, ihi, aAI[q]);
            ri[(fi - 1) * DT + doff + q * 2 + 0] = make_float2(rlo, ilo);
            ri[(fi - 1) * DT + doff + q * 2 + 1] = make_float2(rhi, ihi);
        }
        if (fi <= 127) {           // B = fi+128 in 129..255 (fi=128 -> Nyquist, discard)
            #pragma unroll
            for (int q = 0; q < 4; q++) {
                float rlo, rhi, ilo, ihi;
                UNPACK2(rlo, rhi, aBR[q]);
                UNPACK2(ilo, ihi, aBI[q]);
                ri[(fi + 127) * DT + doff + q * 2 + 0] = make_float2(rlo, ilo);
                ri[(fi + 127) * DT + doff + q * 2 + 1] = make_float2(rhi, ihi);
            }
        }
    }
    __syncthreads();

    // ---- Phase 1b: per-d top-4 |X|^2 (tie -> lower index) ----
    {
        const int lane = tid & 31, wid = tid >> 5;
        const float2* ri = reinterpret_cast<const float2*>(sm.scratch);
        for (int dd = wid * 2; dd < wid * 2 + 2; dd++) {
            int sel0 = -1, sel1 = -1, sel2 = -1, sel3 = -1;
            #pragma unroll
            for (int pass = 0; pass < 4; pass++) {
                float best = -1.f; int bi = 0x7fffffff;
                for (int r = lane; r < F; r += 32) {
                    if (r == sel0 || r == sel1 || r == sel2 || r == sel3) continue;
                    float2 v = ri[r * DT + dd];
                    float a = v.x * v.x + v.y * v.y;
                    if (a > best || (a == best && r < bi)) { best = a; bi = r; }
                }
                #pragma unroll
                for (int off = 16; off > 0; off >>= 1) {
                    float ob = __shfl_down_sync(0xffffffffu, best, off);
                    int   oi = __shfl_down_sync(0xffffffffu, bi,   off);
                    if (ob > best || (ob == best && oi < bi)) { best = ob; bi = oi; }
                }
                bi = __shfl_sync(0xffffffffu, bi, 0);
                if      (pass == 0) sel0 = bi;
                else if (pass == 1) sel1 = bi;
                else if (pass == 2) sel2 = bi;
                else                sel3 = bi;
            }
            if (lane == 0) {
                int s4[4] = { sel0, sel1, sel2, sel3 };
                #pragma unroll
                for (int j = 0; j < 4; j++) {
                    int r = s4[j];
                    float2 v = ri[r * DT + dd];
                    sm.selk[dd][j]  = r + 1;
                    sm.selRe[dd][j] = v.x;
                    sm.selIm[dd][j] = v.y;
                }
            }
        }
    }
    __syncthreads();

    // ---- Phase 2: reconstruct x from e/o, compute x_rem pairwise into scratch ----
    {
        for (int idx = tid; idx < 255 * DT; idx += NTH) {
            int t = (idx >> 4) + 1, dd = idx & 15;
            float e = sm.bufB[t * DT + dd];
            float o = sm.bufB[4096 + t * DT + dd];
            float xt = 0.5f * (e + o);           // x[t]
            float xm = 0.5f * (e - o);           // x[512-t]
            float seP = 0.f, seM = 0.f;
            #pragma unroll
            for (int j = 0; j < 4; j++) {
                int k = sm.selk[dd][j];
                float2 wv = sm.tab[(k * t) & (T - 1)];
                float a  = sm.selRe[dd][j] * wv.x;
                float bq = sm.selIm[dd][j] * wv.y;
                seP += a - bq;                   // season at t
                seM += a + bq;                   // season at 512-t (cos even, sin odd)
            }
            float xrt = xt - SSCALE * seP;
            float xrm = xm - SSCALE * seM;
            sm.scratch[t * DT + dd]       = xrt;
            sm.scratch[(T - t) * DT + dd] = xrm;
            if (t == 1) sm.xrL[dd] = xrm;        // t = 511
        }
        if (tid < 32) {
            int dd = tid & 15;
            if (tid < 16) {                      // t = 0
                float se = 0.f;
                #pragma unroll
                for (int j = 0; j < 4; j++) se += sm.selRe[dd][j];
                float xr = sm.x0row[dd] - SSCALE * se;
                sm.scratch[dd] = xr;
                sm.xr0[dd] = xr;
            } else {                             // t = 256: cos(pi k) = (-1)^k
                float se = 0.f;
                #pragma unroll
                for (int j = 0; j < 4; j++) {
                    float v = sm.selRe[dd][j];
                    se += (sm.selk[dd][j] & 1) ? -v : v;
                }
                sm.scratch[256 * DT + dd] = sm.x256row[dd] - SSCALE * se;
            }
        }
    }
    __syncthreads();

    // ---- Phase 3: segmented parallel prefix sums of x_rem -> cs in bufB ----
    {
        const int dd = tid & 15, seg = tid >> 4;
        const int t0 = seg * 32;
        float s = 0.f;
        #pragma unroll
        for (int i = 0; i < 32; i++) s += sm.scratch[(t0 + i) * DT + dd];
        sm.red[seg * 16 + dd] = s;
    }
    __syncthreads();
    if (tid < 16) {
        float run = 0.f;
        #pragma unroll
        for (int sgi = 0; sgi < 16; sgi++) {
            float v = sm.red[sgi * 16 + tid];
            sm.red[sgi * 16 + tid] = run;
            run += v;
        }
    }
    __syncthreads();
    {
        const int dd = tid & 15, seg = tid >> 4;
        const int t0 = seg * 32;
        float run = sm.red[seg * 16 + dd];
        if (seg == 0) sm.bufB[dd] = 0.f;
        #pragma unroll
        for (int i = 0; i < 32; i++) {
            run += sm.scratch[(t0 + i) * DT + dd];
            sm.bufB[(t0 + i + 1) * DT + dd] = run;
        }
    }
    __syncthreads();

    // ---- Phase 4: moving averages + softmax blend + recomputed season + W_lin ----
    {
        const int dd = tid & 15;
        const float x0 = sm.xr0[dd], xL = sm.xrL[dd];
        float wtr[6], btr[6];
        #pragma unroll
        for (int j = 0; j < 6; j++) { wtr[j] = sm.wt[j]; btr[j] = sm.bt[j]; }
        int   kk[4];
        float kre[4], kim[4];
        #pragma unroll
        for (int j = 0; j < 4; j++) {
            kk[j] = sm.selk[dd][j]; kre[j] = sm.selRe[dd][j]; kim[j] = sm.selIm[dd][j];
        }

        float acc = 0.f;
        const int tb = tid >> 4;
        const float* cs = sm.bufB;
        #pragma unroll 4
        for (int i = 0; i < 32; i++) {
            int t = tb + 16 * i;
            float xr = sm.scratch[t * DT + dd];
            float num = 0.f, den = 0.f;
            const int ksArr[6] = { 4, 8, 12, 16, 24, 32 };
            #pragma unroll
            for (int j = 0; j < 6; j++) {
                const int k = ksArr[j];
                const int h = k >> 1;
                int lo = t - h, hi = t + h - 1;
                int hiC = hi < (T - 1) ? hi : (T - 1);
                int loC = lo > 0 ? lo : 0;
                float s = cs[(hiC + 1) * DT + dd] - cs[loC * DT + dd];
                if (lo < 0)     s = fmaf((float)(-lo), x0, s);
                if (hi > T - 1) s = fmaf((float)(hi - (T - 1)), xL, s);
                float e = __expf(fmaf(xr, wtr[j], btr[j]));
                den += e;
                num = fmaf(s * (1.0f / (float)k), e, num);
            }
            float se = 0.f;
            #pragma unroll
            for (int j = 0; j < 4; j++) {
                float2 wv = sm.tab[(kk[j] * t) & (T - 1)];
                se = fmaf(kre[j], wv.x, se);
                se = fmaf(-kim[j], wv.y, se);
            }
            float xsum = xr + SSCALE2 * se + num / den;
            acc = fmaf(xsum, sm.wl[t], acc);
        }
        sm.red[tid] = acc;
    }
    __syncthreads();

    if (tid < DT) {
        float s = 0.f;
        #pragma unroll
        for (int j = 0; j < NTH / DT; j++) s += sm.red[tid + DT * j];
        g_xtrans[b * D + d0 + tid] = s + bl_g[0];
        __threadfence();
    }
    __syncthreads();

    // ---- Fused finalize: last CTA does router head for all 16 b ----
    if (tid == 0) {
        unsigned int old = atomicAdd(&g_arrive, 1u);
        sm.done_flag = (old == (unsigned)(NCTA - 1)) ? 1 : 0;
    }
    __syncthreads();
    if (sm.done_flag) {
        __threadfence();
        const int lane = tid & 31, wid = tid >> 5;
        #pragma unroll 1
        for (int rep = 0; rep < 2; rep++) {
            const int bb = wid * 2 + rep;
            float aB[8], aN[8];
            #pragma unroll
            for (int m = 0; m < 8; m++) { aB[m] = 0.f; aN[m] = 0.f; }
            for (int d = lane; d < D; d += 32) {
                float xt = g_xtrans[bb * D + d];
                float4 r0 = *reinterpret_cast<const float4*>(Wr + d * 8);
                float4 r1 = *reinterpret_cast<const float4*>(Wr + d * 8 + 4);
                float4 n0 = *reinterpret_cast<const float4*>(Wn + d * 8);
                float4 n1 = *reinterpret_cast<const float4*>(Wn + d * 8 + 4);
                aB[0] = fmaf(xt, r0.x, aB[0]); aB[1] = fmaf(xt, r0.y, aB[1]);
                aB[2] = fmaf(xt, r0.z, aB[2]); aB[3] = fmaf(xt, r0.w, aB[3]);
                aB[4] = fmaf(xt, r1.x, aB[4]); aB[5] = fmaf(xt, r1.y, aB[5]);
                aB[6] = fmaf(xt, r1.z, aB[6]); aB[7] = fmaf(xt, r1.w, aB[7]);
                aN[0] = fmaf(xt, n0.x, aN[0]); aN[1] = fmaf(xt, n0.y, aN[1]);
                aN[2] = fmaf(xt, n0.z, aN[2]); aN[3] = fmaf(xt, n0.w, aN[3]);
                aN[4] = fmaf(xt, n1.x, aN[4]); aN[5] = fmaf(xt, n1.y, aN[5]);
                aN[6] = fmaf(xt, n1.z, aN[6]); aN[7] = fmaf(xt, n1.w, aN[7]);
            }
            #pragma unroll
            for (int m = 0; m < 8; m++) {
                #pragma unroll
                for (int off = 16; off > 0; off >>= 1) {
                    aB[m] += __shfl_down_sync(0xffffffffu, aB[m], off);
                    aN[m] += __shfl_down_sync(0xffffffffu, aN[m], off);
                }
            }
            if (lane == 0) {
                float pw[8];
                float mx = -1e30f;
                #pragma unroll
                for (int m = 0; m < 8; m++) {
                    float z  = aN[m] + bn[m];
                    float sp = (z > 20.f) ? z : log1pf(expf(z));
                    float l  = aB[m] + br[m] + noise[bb * 8 + m] * sp;
                    pw[m] = l;
                    if (l > mx) mx = l;
                }
                float s = 0.f;
                #pragma unroll
                for (int m = 0; m < 8; m++) { pw[m] = expf(pw[m] - mx); s += pw[m]; }
                float inv = 1.f / s;
                #pragma unroll
                for (int m = 0; m < 8; m++) pw[m] *= inv;

                unsigned kept = 0u;
                #pragma unroll
                for (int p = 0; p < 4; p++) {
                    float best = -1.f; int bi = 0;
                    #pragma unroll
                    for (int m = 0; m < 8; m++) {
                        bool free_m = ((kept >> m) & 1u) == 0u;
                        if (free_m && pw[m] > best) { best = pw[m]; bi = m; }
                    }
                    kept |= (1u << bi);
                }
                #pragma unroll
                for (int m = 0; m < 8; m++)
                    out[bb * 8 + m] = ((kept >> m) & 1u) ? pw[m] : 0.f;
            }
        }
        __syncthreads();
        if (tid == 0) g_arrive = 0u;   // reset for next launch/replay
    }
}

extern "C" void kernel_launch(void* const* d_in, const int* in_sizes, int n_in,
                              void* d_out, int out_size) {
    const float* x     = (const float*)d_in[0];
    const float* noise = (const float*)d_in[1];
    const float* Wr    = (const float*)d_in[2];
    const float* br    = (const float*)d_in[3];
    const float* Wn    = (const float*)d_in[4];
    const float* bn    = (const float*)d_in[5];
    const float* wt    = (const float*)d_in[6];
    const float* bt    = (const float*)d_in[7];
    const float* wl    = (const float*)d_in[8];
    const float* bl    = (const float*)d_in[9];
    float* out = (float*)d_out;

    (void)cudaFuncSetAttribute(msr_main, cudaFuncAttributeMaxDynamicSharedMemorySize,
                               (int)sizeof(Smem));
    dim3 grid(NTILES, Bb);
    msr_main<<<grid, NTH, sizeof(Smem)>>>(x, wt, bt, wl, bl,
                                          noise, Wr, br, Wn, bn, out);
}